// round 7
// baseline (speedup 1.0000x reference)
#include <cuda_runtime.h>
#include <cuda_bf16.h>
#include <cstdint>

// LI_no_Spike: u[b,f,t] = clip(tau[f],0,1) * u[b,f,t-1] + x[b,f,t], u[.,.,-1]=0
// x: [B,F,T] fp32 row-major (T innermost), tau: [F] fp32, out: [B,F,T] fp32.
//
// One warp per (b,f) row. Weighted Hillis-Steele warp scan (ratio a^4 between
// lanes), each lane holds a float4 of consecutive timesteps -> fully coalesced
// 512B/warp transactions. All 4 segment loads are front-batched (MLP_p1=4) so
// only one DRAM latency is exposed per warp; the sequential carry chain then
// runs on register-resident data.

static constexpr int T_CONST = 500;           // timesteps
static constexpr int NSEG    = (T_CONST + 127) / 128;   // 4 segments of 128

__global__ __launch_bounds__(256)
void li_scan_kernel(const float* __restrict__ x,
                    const float* __restrict__ tau,
                    float* __restrict__ out,
                    int rows, int F, int T) {
    const int warp_id = (blockIdx.x * blockDim.x + threadIdx.x) >> 5;
    const int lane    = threadIdx.x & 31;
    if (warp_id >= rows) return;

    // Row ratio: clamp tau into [0,1] ("forward" constraint)
    const float a = fminf(fmaxf(__ldg(&tau[warp_id % F]), 0.0f), 1.0f);

    // Powers of a
    const float a2   = a * a;
    const float a3   = a2 * a;
    const float a4   = a2 * a2;
    const float a8   = a4 * a4;
    const float a16  = a8 * a8;
    const float a32  = a16 * a16;
    const float a64  = a32 * a32;
    const float a128 = a64 * a64;

    // a^(4*lane): carry weight at this lane
    float a4l = 1.0f;
    if (lane & 1)  a4l *= a4;
    if (lane & 2)  a4l *= a8;
    if (lane & 4)  a4l *= a16;
    if (lane & 8)  a4l *= a32;
    if (lane & 16) a4l *= a64;

    const float* __restrict__ xr   = x   + (size_t)warp_id * T;
    float*       __restrict__ orow = out + (size_t)warp_id * T;

    const unsigned FULL = 0xFFFFFFFFu;

    // ---- Front-batched loads: 4 independent LDG.E.128 per lane (MLP_p1=4) ----
    float4 v[NSEG];
    bool   act[NSEG];
    #pragma unroll
    for (int s = 0; s < NSEG; s++) {
        const int e = s * 128 + 4 * lane;
        act[s] = (e < T);
        v[s] = act[s] ? *reinterpret_cast<const float4*>(xr + e)
                      : make_float4(0.f, 0.f, 0.f, 0.f);
    }

    // ---- Sequential scan over segments (register-resident data) ----
    float c = 0.0f;  // state entering current segment
    #pragma unroll
    for (int s = 0; s < NSEG; s++) {
        const int e = s * 128 + 4 * lane;

        // Lane-local inclusive scan of 4 elements (state-in = 0)
        const float s0 = v[s].x;
        const float s1 = fmaf(a, s0, v[s].y);
        const float s2 = fmaf(a, s1, v[s].z);
        const float s3 = fmaf(a, s2, v[s].w);

        // Warp-level inclusive scan of lane totals with ratio a^4
        float P = s3;
        {
            float t;
            t = __shfl_up_sync(FULL, P, 1);  if (lane >= 1)  P = fmaf(a4,  t, P);
            t = __shfl_up_sync(FULL, P, 2);  if (lane >= 2)  P = fmaf(a8,  t, P);
            t = __shfl_up_sync(FULL, P, 4);  if (lane >= 4)  P = fmaf(a16, t, P);
            t = __shfl_up_sync(FULL, P, 8);  if (lane >= 8)  P = fmaf(a32, t, P);
            t = __shfl_up_sync(FULL, P, 16); if (lane >= 16) P = fmaf(a64, t, P);
        }

        // State entering this lane's 4 elements: C = P_{lane-1} + a^(4*lane)*c
        float Pprev = __shfl_up_sync(FULL, P, 1);
        if (lane == 0) Pprev = 0.0f;
        const float C = fmaf(a4l, c, Pprev);

        if (act[s]) {
            float4 o;
            o.x = fmaf(a,  C, s0);
            o.y = fmaf(a2, C, s1);
            o.z = fmaf(a3, C, s2);
            o.w = fmaf(a4, C, s3);
            *reinterpret_cast<float4*>(orow + e) = o;
        }

        // Carry: state after lane 31 = P_31 + a^128 * c
        const float P31 = __shfl_sync(FULL, P, 31);
        c = fmaf(a128, c, P31);
    }
}

extern "C" void kernel_launch(void* const* d_in, const int* in_sizes, int n_in,
                              void* d_out, int out_size) {
    const float* x   = (const float*)d_in[0];   // [B*F, T]
    const float* tau = (const float*)d_in[1];   // [F]
    float* out = (float*)d_out;

    const int F    = in_sizes[1];               // 1024
    const int T    = T_CONST;                   // 500
    const int rows = in_sizes[0] / T;           // B*F = 131072

    const int threads = 256;                    // 8 warps/block
    const int warps_per_block = threads / 32;
    const int blocks = (rows + warps_per_block - 1) / warps_per_block;

    li_scan_kernel<<<blocks, threads>>>(x, tau, out, rows, F, T);
}